// round 3
// baseline (speedup 1.0000x reference)
#include <cuda_runtime.h>
#include <math.h>
#include <stdint.h>

#define N_NODES 50000
#define IN_DIM 128
#define OUT_DIM 128
#define HEADS 4
#define HEAD_DIM 32
#define N_EDGES 800000
#define LN_EPS 1e-5f
#define NEG_SLOPE 0.2f

// ---------------- scratch (device globals; no allocation allowed) ----------
__device__ float g_h[(size_t)N_NODES * OUT_DIM];      // x @ W
__device__ float g_asrc[N_NODES * HEADS];
__device__ float g_adst[N_NODES * HEADS];
__device__ int   g_deg[N_NODES];
__device__ int   g_start[N_NODES];
__device__ int   g_cursor[N_NODES];
__device__ int   g_csr[N_EDGES];                      // src ids grouped by dst
__device__ int   g_is64;

// ---------------- dtype detection: int64 vs int32 edge_index ---------------
// int64 little-endian => every odd 32-bit word is a zero high word. 512
// parallel probes over the first 1.6M words (in-bounds either way).
__global__ void detect_kernel(const int* __restrict__ ei) {
    int t = threadIdx.x;
    long long w = 1 + 2LL * (long long)t * 1560LL;    // odd indices < 1.6M
    int nz = (ei[w] != 0);
    int any = __syncthreads_or(nz);
    if (t == 0) g_is64 = any ? 0 : 1;
}

__global__ void zero_deg_kernel() {
    int i = blockIdx.x * blockDim.x + threadIdx.x;
    if (i < N_NODES) g_deg[i] = 0;
}

// ---------------- GEMM: h = x @ W, fused attention logits ------------------
// Block tile: 64 rows x 128 cols. 256 threads, each 4 rows x (4+4) cols.
// Epilogue computes a_src/a_dst per (row, head) via 8-lane shfl reduction.
__global__ __launch_bounds__(256) void gemm_kernel(const float* __restrict__ x,
                                                   const float* __restrict__ W,
                                                   const float* __restrict__ att_src,
                                                   const float* __restrict__ att_dst) {
    extern __shared__ float sm[];
    float* Ws = sm;                       // [128][128]
    float* Xs = sm + IN_DIM * OUT_DIM;    // [64][128]
    int t = threadIdx.x;

    const float4* W4 = reinterpret_cast<const float4*>(W);
    float4* Ws4 = reinterpret_cast<float4*>(Ws);
    for (int i = t; i < (IN_DIM * OUT_DIM) / 4; i += 256) Ws4[i] = W4[i];

    int row0 = blockIdx.x * 64;
    float4* Xs4 = reinterpret_cast<float4*>(Xs);
    const float4* x4 = reinterpret_cast<const float4*>(x);
    for (int i = t; i < (64 * IN_DIM) / 4; i += 256) {
        int r = i >> 5;
        float4 v = make_float4(0.f, 0.f, 0.f, 0.f);
        if (row0 + r < N_NODES) v = x4[(size_t)(row0 + r) * 32 + (i & 31)];
        Xs4[i] = v;
    }
    __syncthreads();

    int tr = (t >> 4) * 4;
    int tc = (t & 15) * 4;                // group0: tc..tc+3, group1: +64
    float acc0[4][4] = {};
    float acc1[4][4] = {};

    #pragma unroll 8
    for (int k = 0; k < IN_DIM; k++) {
        float4 w0 = *reinterpret_cast<const float4*>(&Ws[k * 128 + tc]);
        float4 w1 = *reinterpret_cast<const float4*>(&Ws[k * 128 + tc + 64]);
        #pragma unroll
        for (int i = 0; i < 4; i++) {
            float xv = Xs[(tr + i) * 128 + k];
            acc0[i][0] += xv * w0.x; acc0[i][1] += xv * w0.y;
            acc0[i][2] += xv * w0.z; acc0[i][3] += xv * w0.w;
            acc1[i][0] += xv * w1.x; acc1[i][1] += xv * w1.y;
            acc1[i][2] += xv * w1.z; acc1[i][3] += xv * w1.w;
        }
    }

    #pragma unroll
    for (int i = 0; i < 4; i++) {
        int row = row0 + tr + i;
        if (row < N_NODES) {
            *reinterpret_cast<float4*>(&g_h[(size_t)row * 128 + tc]) =
                make_float4(acc0[i][0], acc0[i][1], acc0[i][2], acc0[i][3]);
            *reinterpret_cast<float4*>(&g_h[(size_t)row * 128 + tc + 64]) =
                make_float4(acc1[i][0], acc1[i][1], acc1[i][2], acc1[i][3]);
        }
    }

    // ---- fused attention logits ----
    // att weights for this thread's columns (flat layout == head-major cols)
    float as0[4], ad0[4], as1[4], ad1[4];
    #pragma unroll
    for (int j = 0; j < 4; j++) {
        as0[j] = __ldg(att_src + tc + j);
        ad0[j] = __ldg(att_dst + tc + j);
        as1[j] = __ldg(att_src + tc + 64 + j);
        ad1[j] = __ldg(att_dst + tc + 64 + j);
    }
    int h0 = tc >> 5;                     // 0 or 1; group1 head = h0+2
    #pragma unroll
    for (int i = 0; i < 4; i++) {
        float ps0 = 0.f, pd0 = 0.f, ps1 = 0.f, pd1 = 0.f;
        #pragma unroll
        for (int j = 0; j < 4; j++) {
            ps0 += acc0[i][j] * as0[j];
            pd0 += acc0[i][j] * ad0[j];
            ps1 += acc1[i][j] * as1[j];
            pd1 += acc1[i][j] * ad1[j];
        }
        #pragma unroll
        for (int o = 1; o < 8; o <<= 1) {
            ps0 += __shfl_xor_sync(0xffffffffu, ps0, o);
            pd0 += __shfl_xor_sync(0xffffffffu, pd0, o);
            ps1 += __shfl_xor_sync(0xffffffffu, ps1, o);
            pd1 += __shfl_xor_sync(0xffffffffu, pd1, o);
        }
        int row = row0 + tr + i;
        if ((t & 7) == 0 && row < N_NODES) {
            g_asrc[row * 4 + h0]     = ps0;
            g_asrc[row * 4 + h0 + 2] = ps1;
            g_adst[row * 4 + h0]     = pd0;
            g_adst[row * 4 + h0 + 2] = pd1;
        }
    }
}

// ---------------- CSR build: histogram -> scan -> scatter ------------------
__global__ __launch_bounds__(256) void hist_kernel(const int* __restrict__ ei) {
    int e = blockIdx.x * blockDim.x + threadIdx.x;
    if (e >= N_EDGES) return;
    int d = g_is64 ? ei[2 * (N_EDGES + e)] : ei[N_EDGES + e];
    atomicAdd(&g_deg[d], 1);
}

__global__ __launch_bounds__(1024) void scan_kernel() {
    __shared__ int smem[1024];
    int t = threadIdx.x;
    int lo = t * 49;
    int hi = min(lo + 49, N_NODES);
    int s = 0;
    for (int i = lo; i < hi; i++) s += g_deg[i];
    smem[t] = s;
    __syncthreads();
    for (int off = 1; off < 1024; off <<= 1) {
        int v = (t >= off) ? smem[t - off] : 0;
        __syncthreads();
        smem[t] += v;
        __syncthreads();
    }
    int run = (t == 0) ? 0 : smem[t - 1];
    for (int i = lo; i < hi; i++) {
        g_start[i]  = run;
        g_cursor[i] = run;
        run += g_deg[i];
    }
}

__global__ __launch_bounds__(256) void scatter_kernel(const int* __restrict__ ei) {
    int e = blockIdx.x * blockDim.x + threadIdx.x;
    if (e >= N_EDGES) return;
    int s, d;
    if (g_is64) { s = ei[2 * e]; d = ei[2 * (N_EDGES + e)]; }
    else        { s = ei[e];     d = ei[N_EDGES + e]; }
    int pos = atomicAdd(&g_cursor[d], 1);
    g_csr[pos] = s;
}

// ---------------- aggregation + epilogue (warp per dst node) ---------------
// Accumulates sum(exp(e)*h[src]) and denom in registers, adds the self-loop,
// normalizes, then bias + LayerNorm + residual + exact GELU.
__global__ __launch_bounds__(256) void agg_kernel(const float* __restrict__ x,
                                                  const float* __restrict__ bias,
                                                  const float* __restrict__ gamma,
                                                  const float* __restrict__ beta,
                                                  float* __restrict__ out) {
    int n = (int)(((size_t)blockIdx.x * blockDim.x + threadIdx.x) >> 5);
    int lane = threadIdx.x & 31;
    if (n >= N_NODES) return;
    int head = lane >> 3;

    float adh      = g_adst[n * 4 + head];
    float ash_self = g_asrc[n * 4 + head];
    int deg = g_deg[n];
    int st  = g_start[n];

    float4 acc = make_float4(0.f, 0.f, 0.f, 0.f);
    float den = 0.f;

    for (int base = 0; base < deg; base += 32) {
        int cnt = min(32, deg - base);
        int s_r = (lane < cnt) ? __ldg(&g_csr[st + base + lane]) : 0;
        #pragma unroll 4
        for (int i = 0; i < cnt; i++) {
            int s = __shfl_sync(0xffffffffu, s_r, i);
            float e = __ldg(&g_asrc[s * 4 + head]) + adh;
            e = e > 0.f ? e : NEG_SLOPE * e;
            float ex = __expf(e);
            float4 hv = __ldg(reinterpret_cast<const float4*>(
                g_h + (size_t)s * 128 + lane * 4));
            acc.x += hv.x * ex; acc.y += hv.y * ex;
            acc.z += hv.z * ex; acc.w += hv.w * ex;
            den += ex;
        }
    }

    // self-loop
    {
        float e = ash_self + adh;
        e = e > 0.f ? e : NEG_SLOPE * e;
        float ex = __expf(e);
        float4 hv = *reinterpret_cast<const float4*>(
            g_h + (size_t)n * 128 + lane * 4);
        acc.x += hv.x * ex; acc.y += hv.y * ex;
        acc.z += hv.z * ex; acc.w += hv.w * ex;
        den += ex;
    }

    float inv = 1.f / den;
    float4 b4 = __ldg(reinterpret_cast<const float4*>(bias + lane * 4));
    float v0 = acc.x * inv + b4.x;
    float v1 = acc.y * inv + b4.y;
    float v2 = acc.z * inv + b4.z;
    float v3 = acc.w * inv + b4.w;

    // LayerNorm over 128 channels (warp allreduce)
    float s = v0 + v1 + v2 + v3;
    #pragma unroll
    for (int o = 16; o > 0; o >>= 1) s += __shfl_xor_sync(0xffffffffu, s, o);
    float mu = s * (1.f / 128.f);
    float d0 = v0 - mu, d1 = v1 - mu, d2 = v2 - mu, d3 = v3 - mu;
    float q = d0 * d0 + d1 * d1 + d2 * d2 + d3 * d3;
    #pragma unroll
    for (int o = 16; o > 0; o >>= 1) q += __shfl_xor_sync(0xffffffffu, q, o);
    float rstd = rsqrtf(q * (1.f / 128.f) + LN_EPS);

    float4 gm = __ldg(reinterpret_cast<const float4*>(gamma + lane * 4));
    float4 bt = __ldg(reinterpret_cast<const float4*>(beta + lane * 4));
    float4 xv = *reinterpret_cast<const float4*>(x + (size_t)n * 128 + lane * 4);

    float h0 = d0 * rstd * gm.x + bt.x + xv.x;
    float h1 = d1 * rstd * gm.y + bt.y + xv.y;
    float h2 = d2 * rstd * gm.z + bt.z + xv.z;
    float h3 = d3 * rstd * gm.w + bt.w + xv.w;

    const float k = 0.70710678118654752f;
    float4 r;
    r.x = 0.5f * h0 * (1.f + erff(h0 * k));
    r.y = 0.5f * h1 * (1.f + erff(h1 * k));
    r.z = 0.5f * h2 * (1.f + erff(h2 * k));
    r.w = 0.5f * h3 * (1.f + erff(h3 * k));
    *reinterpret_cast<float4*>(out + (size_t)n * 128 + lane * 4) = r;
}

// ---------------- launch ----------------------------------------------------
extern "C" void kernel_launch(void* const* d_in, const int* in_sizes, int n_in,
                              void* d_out, int out_size) {
    const float* x       = (const float*)d_in[0];
    const int*   ei      = (const int*)d_in[1];   // int32 or int64 (detected)
    const float* W       = (const float*)d_in[2];
    const float* att_src = (const float*)d_in[3];
    const float* att_dst = (const float*)d_in[4];
    const float* bias    = (const float*)d_in[5];
    const float* gamma   = (const float*)d_in[6];
    const float* beta    = (const float*)d_in[7];
    float* out = (float*)d_out;

    cudaFuncSetAttribute(gemm_kernel, cudaFuncAttributeMaxDynamicSharedMemorySize,
                         98304);

    detect_kernel<<<1, 512>>>(ei);
    zero_deg_kernel<<<(N_NODES + 255) / 256, 256>>>();
    hist_kernel<<<(N_EDGES + 255) / 256, 256>>>(ei);
    gemm_kernel<<<(N_NODES + 63) / 64, 256, 98304>>>(x, W, att_src, att_dst);
    scan_kernel<<<1, 1024>>>();
    scatter_kernel<<<(N_EDGES + 255) / 256, 256>>>(ei);
    agg_kernel<<<(N_NODES + 7) / 8, 256>>>(x, bias, gamma, beta, out);
}

// round 4
// speedup vs baseline: 1.0633x; 1.0633x over previous
#include <cuda_runtime.h>
#include <math.h>
#include <stdint.h>

#define N_NODES 50000
#define IN_DIM 128
#define OUT_DIM 128
#define HEADS 4
#define HEAD_DIM 32
#define N_EDGES 800000
#define LN_EPS 1e-5f
#define NEG_SLOPE 0.2f

// ---------------- scratch (device globals; no allocation allowed) ----------
__device__ float g_h[(size_t)N_NODES * OUT_DIM];      // x @ W
__device__ float g_asrc[N_NODES * HEADS];
__device__ float g_adst[N_NODES * HEADS];
__device__ int   g_deg[N_NODES];
__device__ int   g_start[N_NODES];
__device__ int   g_cursor[N_NODES];
__device__ int   g_csr[N_EDGES];                      // src ids grouped by dst
__device__ int   g_is64;

// ---------------- dtype detection: int64 vs int32 edge_index ---------------
__global__ void detect_kernel(const int* __restrict__ ei) {
    int t = threadIdx.x;
    long long w = 1 + 2LL * (long long)t * 1560LL;    // odd word indices < 1.6M
    int nz = (ei[w] != 0);
    int any = __syncthreads_or(nz);
    if (t == 0) g_is64 = any ? 0 : 1;
}

__global__ void zero_deg_kernel() {
    int i = blockIdx.x * blockDim.x + threadIdx.x;
    if (i < N_NODES) g_deg[i] = 0;
}

// ---------------- GEMM: h = x @ W, fused attention logits ------------------
// 64 rows x 128 cols per block; 256 threads, each 4 rows x (4+4) cols.
// W staged in 2x16KB double-buffered cp.async chunks (32 k-rows each);
// total smem 64KB -> 3 CTAs/SM.
__global__ __launch_bounds__(256) void gemm_kernel(const float* __restrict__ x,
                                                   const float* __restrict__ W,
                                                   const float* __restrict__ att_src,
                                                   const float* __restrict__ att_dst) {
    extern __shared__ float sm[];
    float* Xs = sm;                         // [64][128] = 32KB
    float* Wb[2] = { sm + 8192, sm + 8192 + 4096 };   // 2 x [32][128] = 32KB
    int t = threadIdx.x;
    int row0 = blockIdx.x * 64;

    const float4* x4 = reinterpret_cast<const float4*>(x);
    const float4* W4 = reinterpret_cast<const float4*>(W);

    // stage Xs (2048 float4) + W chunk0 via cp.async  -> group 0
    #pragma unroll
    for (int i = 0; i < 8; i++) {
        int idx = t + i * 256;
        int r = idx >> 5, c = idx & 31;
        int row = row0 + r;
        const float4* g = x4 + (size_t)min(row, N_NODES - 1) * 32 + c;
        uint32_t sa = (uint32_t)__cvta_generic_to_shared(Xs + idx * 4);
        int sz = (row < N_NODES) ? 16 : 0;
        asm volatile("cp.async.cg.shared.global [%0], [%1], 16, %2;"
                     :: "r"(sa), "l"(g), "r"(sz));
    }
    #pragma unroll
    for (int i = 0; i < 4; i++) {
        int idx = t + i * 256;
        uint32_t sa = (uint32_t)__cvta_generic_to_shared(Wb[0] + idx * 4);
        asm volatile("cp.async.cg.shared.global [%0], [%1], 16;"
                     :: "r"(sa), "l"(W4 + idx));
    }
    asm volatile("cp.async.commit_group;");
    // W chunk1 -> group 1
    #pragma unroll
    for (int i = 0; i < 4; i++) {
        int idx = t + i * 256;
        uint32_t sa = (uint32_t)__cvta_generic_to_shared(Wb[1] + idx * 4);
        asm volatile("cp.async.cg.shared.global [%0], [%1], 16;"
                     :: "r"(sa), "l"(W4 + 1024 + idx));
    }
    asm volatile("cp.async.commit_group;");

    int tr = (t >> 4) * 4;
    int tc = (t & 15) * 4;                  // group0: tc..tc+3, group1: +64
    float acc0[4][4] = {};
    float acc1[4][4] = {};

    #pragma unroll
    for (int c = 0; c < 4; c++) {
        if (c == 3) asm volatile("cp.async.wait_group 0;");
        else        asm volatile("cp.async.wait_group 1;");
        __syncthreads();

        const float* Wc = Wb[c & 1];
        #pragma unroll 8
        for (int kk = 0; kk < 32; kk++) {
            int k = c * 32 + kk;
            float4 w0 = *reinterpret_cast<const float4*>(&Wc[kk * 128 + tc]);
            float4 w1 = *reinterpret_cast<const float4*>(&Wc[kk * 128 + tc + 64]);
            #pragma unroll
            for (int i = 0; i < 4; i++) {
                float xv = Xs[(tr + i) * 128 + k];
                acc0[i][0] += xv * w0.x; acc0[i][1] += xv * w0.y;
                acc0[i][2] += xv * w0.z; acc0[i][3] += xv * w0.w;
                acc1[i][0] += xv * w1.x; acc1[i][1] += xv * w1.y;
                acc1[i][2] += xv * w1.z; acc1[i][3] += xv * w1.w;
            }
        }

        if (c < 2) {   // prefetch chunk c+2 into the buffer just freed
            __syncthreads();
            #pragma unroll
            for (int i = 0; i < 4; i++) {
                int idx = t + i * 256;
                uint32_t sa = (uint32_t)__cvta_generic_to_shared(Wb[c & 1] + idx * 4);
                asm volatile("cp.async.cg.shared.global [%0], [%1], 16;"
                             :: "r"(sa), "l"(W4 + (c + 2) * 1024 + idx));
            }
            asm volatile("cp.async.commit_group;");
        }
    }

    #pragma unroll
    for (int i = 0; i < 4; i++) {
        int row = row0 + tr + i;
        if (row < N_NODES) {
            *reinterpret_cast<float4*>(&g_h[(size_t)row * 128 + tc]) =
                make_float4(acc0[i][0], acc0[i][1], acc0[i][2], acc0[i][3]);
            *reinterpret_cast<float4*>(&g_h[(size_t)row * 128 + tc + 64]) =
                make_float4(acc1[i][0], acc1[i][1], acc1[i][2], acc1[i][3]);
        }
    }

    // ---- fused attention logits ----
    float as0[4], ad0[4], as1[4], ad1[4];
    #pragma unroll
    for (int j = 0; j < 4; j++) {
        as0[j] = __ldg(att_src + tc + j);
        ad0[j] = __ldg(att_dst + tc + j);
        as1[j] = __ldg(att_src + tc + 64 + j);
        ad1[j] = __ldg(att_dst + tc + 64 + j);
    }
    int h0 = tc >> 5;                       // 0 or 1; group1 head = h0+2
    #pragma unroll
    for (int i = 0; i < 4; i++) {
        float ps0 = 0.f, pd0 = 0.f, ps1 = 0.f, pd1 = 0.f;
        #pragma unroll
        for (int j = 0; j < 4; j++) {
            ps0 += acc0[i][j] * as0[j];
            pd0 += acc0[i][j] * ad0[j];
            ps1 += acc1[i][j] * as1[j];
            pd1 += acc1[i][j] * ad1[j];
        }
        #pragma unroll
        for (int o = 1; o < 8; o <<= 1) {
            ps0 += __shfl_xor_sync(0xffffffffu, ps0, o);
            pd0 += __shfl_xor_sync(0xffffffffu, pd0, o);
            ps1 += __shfl_xor_sync(0xffffffffu, ps1, o);
            pd1 += __shfl_xor_sync(0xffffffffu, pd1, o);
        }
        int row = row0 + tr + i;
        if ((t & 7) == 0 && row < N_NODES) {
            g_asrc[row * 4 + h0]     = ps0;
            g_asrc[row * 4 + h0 + 2] = ps1;
            g_adst[row * 4 + h0]     = pd0;
            g_adst[row * 4 + h0 + 2] = pd1;
        }
    }
}

// ---------------- CSR build: histogram -> scan -> scatter ------------------
__global__ __launch_bounds__(256) void hist_kernel(const int* __restrict__ ei) {
    int e = blockIdx.x * blockDim.x + threadIdx.x;
    if (e >= N_EDGES) return;
    int d = g_is64 ? ei[2 * (N_EDGES + e)] : ei[N_EDGES + e];
    atomicAdd(&g_deg[d], 1);
}

__global__ __launch_bounds__(1024) void scan_kernel() {
    __shared__ int smem[1024];
    int t = threadIdx.x;
    int lo = t * 49;
    int hi = min(lo + 49, N_NODES);
    int s = 0;
    for (int i = lo; i < hi; i++) s += g_deg[i];
    smem[t] = s;
    __syncthreads();
    for (int off = 1; off < 1024; off <<= 1) {
        int v = (t >= off) ? smem[t - off] : 0;
        __syncthreads();
        smem[t] += v;
        __syncthreads();
    }
    int run = (t == 0) ? 0 : smem[t - 1];
    for (int i = lo; i < hi; i++) {
        g_start[i]  = run;
        g_cursor[i] = run;
        run += g_deg[i];
    }
}

__global__ __launch_bounds__(256) void scatter_kernel(const int* __restrict__ ei) {
    int e = blockIdx.x * blockDim.x + threadIdx.x;
    if (e >= N_EDGES) return;
    int s, d;
    if (g_is64) { s = ei[2 * e]; d = ei[2 * (N_EDGES + e)]; }
    else        { s = ei[e];     d = ei[N_EDGES + e]; }
    int pos = atomicAdd(&g_cursor[d], 1);
    g_csr[pos] = s;
}

// ---------------- aggregation + epilogue (warp per dst node) ---------------
// Phase A: each lane owns one edge -> stage 4 head-exps in smem.
// Phase B: tight pipelined gather of h[src] with staged weights.
__global__ __launch_bounds__(256) void agg_kernel(const float* __restrict__ x,
                                                  const float* __restrict__ bias,
                                                  const float* __restrict__ gamma,
                                                  const float* __restrict__ beta,
                                                  float* __restrict__ out) {
    __shared__ float s_ex[8][128];          // [warp][edge*4+head]
    int n = (int)(((size_t)blockIdx.x * blockDim.x + threadIdx.x) >> 5);
    int lane = threadIdx.x & 31;
    int w = (threadIdx.x >> 5);
    if (n >= N_NODES) return;
    int head = lane >> 3;

    float4 ad4 = *reinterpret_cast<const float4*>(g_adst + (size_t)n * 4);
    float adh = head == 0 ? ad4.x : (head == 1 ? ad4.y : (head == 2 ? ad4.z : ad4.w));
    int deg = g_deg[n];
    int st  = g_start[n];

    float4 acc = make_float4(0.f, 0.f, 0.f, 0.f);
    float den = 0.f;

    for (int base = 0; base < deg; base += 32) {
        int rem = deg - base;
        int idx = base + ((lane < rem) ? lane : (rem - 1));   // alias tail
        bool valid = lane < rem;
        int s_l = __ldg(&g_csr[st + idx]);

        // phase A: 4 head-exps for my edge
        float4 as4 = __ldg(reinterpret_cast<const float4*>(g_asrc + (size_t)s_l * 4));
        float e0 = as4.x + ad4.x, e1 = as4.y + ad4.y;
        float e2 = as4.z + ad4.z, e3 = as4.w + ad4.w;
        e0 = e0 > 0.f ? e0 : NEG_SLOPE * e0;
        e1 = e1 > 0.f ? e1 : NEG_SLOPE * e1;
        e2 = e2 > 0.f ? e2 : NEG_SLOPE * e2;
        e3 = e3 > 0.f ? e3 : NEG_SLOPE * e3;
        float4 ex4;
        ex4.x = valid ? __expf(e0) : 0.f;
        ex4.y = valid ? __expf(e1) : 0.f;
        ex4.z = valid ? __expf(e2) : 0.f;
        ex4.w = valid ? __expf(e3) : 0.f;
        *reinterpret_cast<float4*>(&s_ex[w][lane * 4]) = ex4;
        __syncwarp();

        // phase B: pipelined gather; trip count rounded to 4 (weights are 0
        // past rem, src aliased to last valid edge -> L1 hits, no extra L2)
        int cnt4 = min(32, (rem + 3) & ~3);
        #pragma unroll 4
        for (int i = 0; i < cnt4; i++) {
            int s = __shfl_sync(0xffffffffu, s_l, i);
            float ex = s_ex[w][i * 4 + head];
            float4 hv = __ldg(reinterpret_cast<const float4*>(
                g_h + (size_t)s * 128 + lane * 4));
            acc.x += hv.x * ex; acc.y += hv.y * ex;
            acc.z += hv.z * ex; acc.w += hv.w * ex;
            den += ex;
        }
        __syncwarp();
    }

    // self-loop
    {
        float ash = g_asrc[n * 4 + head];
        float e = ash + adh;
        e = e > 0.f ? e : NEG_SLOPE * e;
        float ex = __expf(e);
        float4 hv = *reinterpret_cast<const float4*>(
            g_h + (size_t)n * 128 + lane * 4);
        acc.x += hv.x * ex; acc.y += hv.y * ex;
        acc.z += hv.z * ex; acc.w += hv.w * ex;
        den += ex;
    }

    float inv = 1.f / den;
    float4 b4 = __ldg(reinterpret_cast<const float4*>(bias + lane * 4));
    float v0 = acc.x * inv + b4.x;
    float v1 = acc.y * inv + b4.y;
    float v2 = acc.z * inv + b4.z;
    float v3 = acc.w * inv + b4.w;

    // LayerNorm over 128 channels (warp allreduce)
    float s = v0 + v1 + v2 + v3;
    #pragma unroll
    for (int o = 16; o > 0; o >>= 1) s += __shfl_xor_sync(0xffffffffu, s, o);
    float mu = s * (1.f / 128.f);
    float d0 = v0 - mu, d1 = v1 - mu, d2 = v2 - mu, d3 = v3 - mu;
    float q = d0 * d0 + d1 * d1 + d2 * d2 + d3 * d3;
    #pragma unroll
    for (int o = 16; o > 0; o >>= 1) q += __shfl_xor_sync(0xffffffffu, q, o);
    float rstd = rsqrtf(q * (1.f / 128.f) + LN_EPS);

    float4 gm = __ldg(reinterpret_cast<const float4*>(gamma + lane * 4));
    float4 bt = __ldg(reinterpret_cast<const float4*>(beta + lane * 4));
    float4 xv = *reinterpret_cast<const float4*>(x + (size_t)n * 128 + lane * 4);

    float h0 = d0 * rstd * gm.x + bt.x + xv.x;
    float h1 = d1 * rstd * gm.y + bt.y + xv.y;
    float h2 = d2 * rstd * gm.z + bt.z + xv.z;
    float h3 = d3 * rstd * gm.w + bt.w + xv.w;

    const float kk = 0.70710678118654752f;
    float4 r;
    r.x = 0.5f * h0 * (1.f + erff(h0 * kk));
    r.y = 0.5f * h1 * (1.f + erff(h1 * kk));
    r.z = 0.5f * h2 * (1.f + erff(h2 * kk));
    r.w = 0.5f * h3 * (1.f + erff(h3 * kk));
    *reinterpret_cast<float4*>(out + (size_t)n * 128 + lane * 4) = r;
}

// ---------------- launch ----------------------------------------------------
extern "C" void kernel_launch(void* const* d_in, const int* in_sizes, int n_in,
                              void* d_out, int out_size) {
    const float* x       = (const float*)d_in[0];
    const int*   ei      = (const int*)d_in[1];   // int32 or int64 (detected)
    const float* W       = (const float*)d_in[2];
    const float* att_src = (const float*)d_in[3];
    const float* att_dst = (const float*)d_in[4];
    const float* bias    = (const float*)d_in[5];
    const float* gamma   = (const float*)d_in[6];
    const float* beta    = (const float*)d_in[7];
    float* out = (float*)d_out;

    cudaFuncSetAttribute(gemm_kernel, cudaFuncAttributeMaxDynamicSharedMemorySize,
                         65536);

    detect_kernel<<<1, 512>>>(ei);
    zero_deg_kernel<<<(N_NODES + 255) / 256, 256>>>();
    hist_kernel<<<(N_EDGES + 255) / 256, 256>>>(ei);
    gemm_kernel<<<(N_NODES + 63) / 64, 256, 65536>>>(x, W, att_src, att_dst);
    scan_kernel<<<1, 1024>>>();
    scatter_kernel<<<(N_EDGES + 255) / 256, 256>>>(ei);
    agg_kernel<<<(N_NODES + 7) / 8, 256>>>(x, bias, gamma, beta, out);
}

// round 8
// speedup vs baseline: 1.1113x; 1.0451x over previous
#include <cuda_runtime.h>
#include <cuda_fp16.h>
#include <math.h>
#include <stdint.h>

#define N_NODES 50000
#define IN_DIM 128
#define OUT_DIM 128
#define HEADS 4
#define HEAD_DIM 32
#define N_EDGES 800000
#define LN_EPS 1e-5f
#define NEG_SLOPE 0.2f

// ---------------- scratch (device globals; no allocation allowed) ----------
__device__ __half g_hh[(size_t)N_NODES * OUT_DIM];    // x @ W in fp16
__device__ float g_asrc[N_NODES * HEADS];
__device__ float g_adst[N_NODES * HEADS];
__device__ int   g_deg[N_NODES];
__device__ int   g_start[N_NODES];
__device__ int   g_cursor[N_NODES];
__device__ int   g_csr[N_EDGES];                      // src ids grouped by dst
__device__ int   g_is64;

union H2x2 { uint2 u; __half2 h[2]; };

// ---------------- dtype detection: int64 vs int32 edge_index ---------------
__global__ void detect_kernel(const int* __restrict__ ei) {
    int t = threadIdx.x;
    long long w = 1 + 2LL * (long long)t * 1560LL;    // odd word indices < 1.6M
    int nz = (ei[w] != 0);
    int any = __syncthreads_or(nz);
    if (t == 0) g_is64 = any ? 0 : 1;
}

__global__ void zero_deg_kernel() {
    int i = blockIdx.x * blockDim.x + threadIdx.x;
    if (i < N_NODES) g_deg[i] = 0;
}

// ---------------- GEMM: h = x @ W (fp32 compute, fp16 store) ---------------
// 64 rows x 128 cols per block; 256 threads, each 4 rows x (4+4) cols.
// W double-buffered via cp.async; fused attention logits from fp32 accs.
__global__ __launch_bounds__(256) void gemm_kernel(const float* __restrict__ x,
                                                   const float* __restrict__ W,
                                                   const float* __restrict__ att_src,
                                                   const float* __restrict__ att_dst) {
    extern __shared__ float sm[];
    float* Xs = sm;                         // [64][128] = 32KB
    float* Wb[2] = { sm + 8192, sm + 8192 + 4096 };   // 2 x [32][128] = 32KB
    int t = threadIdx.x;
    int row0 = blockIdx.x * 64;

    const float4* x4 = reinterpret_cast<const float4*>(x);
    const float4* W4 = reinterpret_cast<const float4*>(W);

    #pragma unroll
    for (int i = 0; i < 8; i++) {
        int idx = t + i * 256;
        int r = idx >> 5, c = idx & 31;
        int row = row0 + r;
        const float4* g = x4 + (size_t)min(row, N_NODES - 1) * 32 + c;
        uint32_t sa = (uint32_t)__cvta_generic_to_shared(Xs + idx * 4);
        int sz = (row < N_NODES) ? 16 : 0;
        asm volatile("cp.async.cg.shared.global [%0], [%1], 16, %2;"
                     :: "r"(sa), "l"(g), "r"(sz));
    }
    #pragma unroll
    for (int i = 0; i < 4; i++) {
        int idx = t + i * 256;
        uint32_t sa = (uint32_t)__cvta_generic_to_shared(Wb[0] + idx * 4);
        asm volatile("cp.async.cg.shared.global [%0], [%1], 16;"
                     :: "r"(sa), "l"(W4 + idx));
    }
    asm volatile("cp.async.commit_group;");
    #pragma unroll
    for (int i = 0; i < 4; i++) {
        int idx = t + i * 256;
        uint32_t sa = (uint32_t)__cvta_generic_to_shared(Wb[1] + idx * 4);
        asm volatile("cp.async.cg.shared.global [%0], [%1], 16;"
                     :: "r"(sa), "l"(W4 + 1024 + idx));
    }
    asm volatile("cp.async.commit_group;");

    int tr = (t >> 4) * 4;
    int tc = (t & 15) * 4;                  // group0: tc..tc+3, group1: +64
    float acc0[4][4] = {};
    float acc1[4][4] = {};

    #pragma unroll
    for (int c = 0; c < 4; c++) {
        if (c == 3) asm volatile("cp.async.wait_group 0;");
        else        asm volatile("cp.async.wait_group 1;");
        __syncthreads();

        const float* Wc = Wb[c & 1];
        #pragma unroll 8
        for (int kk = 0; kk < 32; kk++) {
            int k = c * 32 + kk;
            float4 w0 = *reinterpret_cast<const float4*>(&Wc[kk * 128 + tc]);
            float4 w1 = *reinterpret_cast<const float4*>(&Wc[kk * 128 + tc + 64]);
            #pragma unroll
            for (int i = 0; i < 4; i++) {
                float xv = Xs[(tr + i) * 128 + k];
                acc0[i][0] += xv * w0.x; acc0[i][1] += xv * w0.y;
                acc0[i][2] += xv * w0.z; acc0[i][3] += xv * w0.w;
                acc1[i][0] += xv * w1.x; acc1[i][1] += xv * w1.y;
                acc1[i][2] += xv * w1.z; acc1[i][3] += xv * w1.w;
            }
        }

        if (c < 2) {
            __syncthreads();
            #pragma unroll
            for (int i = 0; i < 4; i++) {
                int idx = t + i * 256;
                uint32_t sa = (uint32_t)__cvta_generic_to_shared(Wb[c & 1] + idx * 4);
                asm volatile("cp.async.cg.shared.global [%0], [%1], 16;"
                             :: "r"(sa), "l"(W4 + (c + 2) * 1024 + idx));
            }
            asm volatile("cp.async.commit_group;");
        }
    }

    #pragma unroll
    for (int i = 0; i < 4; i++) {
        int row = row0 + tr + i;
        if (row < N_NODES) {
            H2x2 v0, v1;
            v0.h[0] = __floats2half2_rn(acc0[i][0], acc0[i][1]);
            v0.h[1] = __floats2half2_rn(acc0[i][2], acc0[i][3]);
            v1.h[0] = __floats2half2_rn(acc1[i][0], acc1[i][1]);
            v1.h[1] = __floats2half2_rn(acc1[i][2], acc1[i][3]);
            *reinterpret_cast<uint2*>(&g_hh[(size_t)row * 128 + tc])      = v0.u;
            *reinterpret_cast<uint2*>(&g_hh[(size_t)row * 128 + tc + 64]) = v1.u;
        }
    }

    // ---- fused attention logits (fp32 accs) ----
    float as0[4], ad0[4], as1[4], ad1[4];
    #pragma unroll
    for (int j = 0; j < 4; j++) {
        as0[j] = __ldg(att_src + tc + j);
        ad0[j] = __ldg(att_dst + tc + j);
        as1[j] = __ldg(att_src + tc + 64 + j);
        ad1[j] = __ldg(att_dst + tc + 64 + j);
    }
    int h0 = tc >> 5;                       // 0 or 1; group1 head = h0+2
    #pragma unroll
    for (int i = 0; i < 4; i++) {
        float ps0 = 0.f, pd0 = 0.f, ps1 = 0.f, pd1 = 0.f;
        #pragma unroll
        for (int j = 0; j < 4; j++) {
            ps0 += acc0[i][j] * as0[j];
            pd0 += acc0[i][j] * ad0[j];
            ps1 += acc1[i][j] * as1[j];
            pd1 += acc1[i][j] * ad1[j];
        }
        #pragma unroll
        for (int o = 1; o < 8; o <<= 1) {
            ps0 += __shfl_xor_sync(0xffffffffu, ps0, o);
            pd0 += __shfl_xor_sync(0xffffffffu, pd0, o);
            ps1 += __shfl_xor_sync(0xffffffffu, ps1, o);
            pd1 += __shfl_xor_sync(0xffffffffu, pd1, o);
        }
        int row = row0 + tr + i;
        if ((t & 7) == 0 && row < N_NODES) {
            g_asrc[row * 4 + h0]     = ps0;
            g_asrc[row * 4 + h0 + 2] = ps1;
            g_adst[row * 4 + h0]     = pd0;
            g_adst[row * 4 + h0 + 2] = pd1;
        }
    }
}

// ---------------- CSR build: histogram -> scan -> scatter ------------------
__global__ __launch_bounds__(256) void hist_kernel(const int* __restrict__ ei) {
    int e = blockIdx.x * blockDim.x + threadIdx.x;
    if (e >= N_EDGES) return;
    int d = g_is64 ? ei[2 * (N_EDGES + e)] : ei[N_EDGES + e];
    atomicAdd(&g_deg[d], 1);
}

__global__ __launch_bounds__(1024) void scan_kernel() {
    __shared__ int smem[1024];
    int t = threadIdx.x;
    int lo = t * 49;
    int hi = min(lo + 49, N_NODES);
    int s = 0;
    for (int i = lo; i < hi; i++) s += g_deg[i];
    smem[t] = s;
    __syncthreads();
    for (int off = 1; off < 1024; off <<= 1) {
        int v = (t >= off) ? smem[t - off] : 0;
        __syncthreads();
        smem[t] += v;
        __syncthreads();
    }
    int run = (t == 0) ? 0 : smem[t - 1];
    for (int i = lo; i < hi; i++) {
        g_start[i]  = run;
        g_cursor[i] = run;
        run += g_deg[i];
    }
}

__global__ __launch_bounds__(256) void scatter_kernel(const int* __restrict__ ei) {
    int e = blockIdx.x * blockDim.x + threadIdx.x;
    if (e >= N_EDGES) return;
    int s, d;
    if (g_is64) { s = ei[2 * e]; d = ei[2 * (N_EDGES + e)]; }
    else        { s = ei[e];     d = ei[N_EDGES + e]; }
    int pos = atomicAdd(&g_cursor[d], 1);
    g_csr[pos] = s;
}

// ---------------- aggregation + epilogue (warp per dst node) ---------------
// Phase A: each lane owns one edge -> stage 4 head-exps in smem.
// Phase B: pipelined fp16 gather (256B/edge/warp) with staged weights.
__global__ __launch_bounds__(256) void agg_kernel(const float* __restrict__ x,
                                                  const float* __restrict__ bias,
                                                  const float* __restrict__ gamma,
                                                  const float* __restrict__ beta,
                                                  float* __restrict__ out) {
    __shared__ float s_ex[8][128];          // [warp][edge*4+head]
    int n = (int)(((size_t)blockIdx.x * blockDim.x + threadIdx.x) >> 5);
    int lane = threadIdx.x & 31;
    int w = (threadIdx.x >> 5);
    if (n >= N_NODES) return;
    int head = lane >> 3;

    float4 ad4 = *reinterpret_cast<const float4*>(g_adst + (size_t)n * 4);
    float adh = head == 0 ? ad4.x : (head == 1 ? ad4.y : (head == 2 ? ad4.z : ad4.w));
    int deg = g_deg[n];
    int st  = g_start[n];

    float4 acc = make_float4(0.f, 0.f, 0.f, 0.f);
    float den = 0.f;

    for (int base = 0; base < deg; base += 32) {
        int rem = deg - base;
        int idx = base + ((lane < rem) ? lane : (rem - 1));   // alias tail
        bool valid = lane < rem;
        int s_l = __ldg(&g_csr[st + idx]);

        // phase A: 4 head-exps for my edge
        float4 as4 = __ldg(reinterpret_cast<const float4*>(g_asrc + (size_t)s_l * 4));
        float e0 = as4.x + ad4.x, e1 = as4.y + ad4.y;
        float e2 = as4.z + ad4.z, e3 = as4.w + ad4.w;
        e0 = e0 > 0.f ? e0 : NEG_SLOPE * e0;
        e1 = e1 > 0.f ? e1 : NEG_SLOPE * e1;
        e2 = e2 > 0.f ? e2 : NEG_SLOPE * e2;
        e3 = e3 > 0.f ? e3 : NEG_SLOPE * e3;
        float4 ex4;
        ex4.x = valid ? __expf(e0) : 0.f;
        ex4.y = valid ? __expf(e1) : 0.f;
        ex4.z = valid ? __expf(e2) : 0.f;
        ex4.w = valid ? __expf(e3) : 0.f;
        *reinterpret_cast<float4*>(&s_ex[w][lane * 4]) = ex4;
        __syncwarp();

        // phase B: pipelined fp16 gather; trip rounded to 8 (tail aliased,
        // ex = 0, L1 hits only)
        int cnt8 = min(32, (rem + 7) & ~7);
        #pragma unroll 8
        for (int i = 0; i < cnt8; i++) {
            int s = __shfl_sync(0xffffffffu, s_l, i);
            float ex = s_ex[w][i * 4 + head];
            H2x2 v;
            v.u = __ldg(reinterpret_cast<const uint2*>(
                g_hh + (size_t)s * 128 + lane * 4));
            float2 f0 = __half22float2(v.h[0]);
            float2 f1 = __half22float2(v.h[1]);
            acc.x += f0.x * ex; acc.y += f0.y * ex;
            acc.z += f1.x * ex; acc.w += f1.y * ex;
            den += ex;
        }
        __syncwarp();
    }

    // self-loop
    {
        float ash = g_asrc[n * 4 + head];
        float e = ash + adh;
        e = e > 0.f ? e : NEG_SLOPE * e;
        float ex = __expf(e);
        H2x2 v;
        v.u = *reinterpret_cast<const uint2*>(g_hh + (size_t)n * 128 + lane * 4);
        float2 f0 = __half22float2(v.h[0]);
        float2 f1 = __half22float2(v.h[1]);
        acc.x += f0.x * ex; acc.y += f0.y * ex;
        acc.z += f1.x * ex; acc.w += f1.y * ex;
        den += ex;
    }

    float inv = 1.f / den;
    float4 b4 = __ldg(reinterpret_cast<const float4*>(bias + lane * 4));
    float v0 = acc.x * inv + b4.x;
    float v1 = acc.y * inv + b4.y;
    float v2 = acc.z * inv + b4.z;
    float v3 = acc.w * inv + b4.w;

    // LayerNorm over 128 channels (warp allreduce)
    float s = v0 + v1 + v2 + v3;
    #pragma unroll
    for (int o = 16; o > 0; o >>= 1) s += __shfl_xor_sync(0xffffffffu, s, o);
    float mu = s * (1.f / 128.f);
    float d0 = v0 - mu, d1 = v1 - mu, d2 = v2 - mu, d3 = v3 - mu;
    float q = d0 * d0 + d1 * d1 + d2 * d2 + d3 * d3;
    #pragma unroll
    for (int o = 16; o > 0; o >>= 1) q += __shfl_xor_sync(0xffffffffu, q, o);
    float rstd = rsqrtf(q * (1.f / 128.f) + LN_EPS);

    float4 gm = __ldg(reinterpret_cast<const float4*>(gamma + lane * 4));
    float4 bt = __ldg(reinterpret_cast<const float4*>(beta + lane * 4));
    float4 xv = *reinterpret_cast<const float4*>(x + (size_t)n * 128 + lane * 4);

    float h0 = d0 * rstd * gm.x + bt.x + xv.x;
    float h1 = d1 * rstd * gm.y + bt.y + xv.y;
    float h2 = d2 * rstd * gm.z + bt.z + xv.z;
    float h3 = d3 * rstd * gm.w + bt.w + xv.w;

    const float kk = 0.70710678118654752f;
    float4 r;
    r.x = 0.5f * h0 * (1.f + erff(h0 * kk));
    r.y = 0.5f * h1 * (1.f + erff(h1 * kk));
    r.z = 0.5f * h2 * (1.f + erff(h2 * kk));
    r.w = 0.5f * h3 * (1.f + erff(h3 * kk));
    *reinterpret_cast<float4*>(out + (size_t)n * 128 + lane * 4) = r;
}

// ---------------- launch ----------------------------------------------------
extern "C" void kernel_launch(void* const* d_in, const int* in_sizes, int n_in,
                              void* d_out, int out_size) {
    const float* x       = (const float*)d_in[0];
    const int*   ei      = (const int*)d_in[1];   // int32 or int64 (detected)
    const float* W       = (const float*)d_in[2];
    const float* att_src = (const float*)d_in[3];
    const float* att_dst = (const float*)d_in[4];
    const float* bias    = (const float*)d_in[5];
    const float* gamma   = (const float*)d_in[6];
    const float* beta    = (const float*)d_in[7];
    float* out = (float*)d_out;

    cudaFuncSetAttribute(gemm_kernel, cudaFuncAttributeMaxDynamicSharedMemorySize,
                         65536);

    detect_kernel<<<1, 512>>>(ei);
    zero_deg_kernel<<<(N_NODES + 255) / 256, 256>>>();
    hist_kernel<<<(N_EDGES + 255) / 256, 256>>>(ei);
    gemm_kernel<<<(N_NODES + 63) / 64, 256, 65536>>>(x, W, att_src, att_dst);
    scan_kernel<<<1, 1024>>>();
    scatter_kernel<<<(N_EDGES + 255) / 256, 256>>>(ei);
    agg_kernel<<<(N_NODES + 7) / 8, 256>>>(x, bias, gamma, beta, out);
}